// round 7
// baseline (speedup 1.0000x reference)
#include <cuda_runtime.h>
#include <math.h>

#define NP_MAX     1048576
#define TABLE_SIZE 524288
#define TMASK      (TABLE_SIZE - 1)
#define NUM_LEVELS 8
#define TPB        256
#define W0F        30.0f
#define NSM        148

typedef unsigned long long u64t;

// Encoding scratch, SoA: g_enc[c*N + n], c in [0,32)
__device__ float g_enc[NUM_LEVELS * 4 * NP_MAX];

struct Res8 { float r[8]; };

// ---------------------------------------------------------------------------
// Packed f32x2 helpers (PTX-only; ptxas never auto-fuses FFMA2).
// Two independent .rn fp32 FMAs per instruction -> bit-identical to scalar.
// ---------------------------------------------------------------------------
__device__ __forceinline__ u64t pack2(float x) {
    u64t r; unsigned xi = __float_as_uint(x);
    asm("mov.b64 %0, {%1, %1};" : "=l"(r) : "r"(xi));
    return r;
}
__device__ __forceinline__ u64t ffma2(u64t a, u64t b, u64t c) {
    u64t d;
    asm("fma.rn.f32x2 %0, %1, %2, %3;" : "=l"(d) : "l"(a), "l"(b), "l"(c));
    return d;
}
__device__ __forceinline__ float2 unpack2(u64t v) {
    unsigned lo, hi;
    asm("mov.b64 {%0, %1}, %2;" : "=r"(lo), "=r"(hi) : "l"(v));
    return make_float2(__uint_as_float(lo), __uint_as_float(hi));
}

// ---------------------------------------------------------------------------
// Accurate sin for |x| <= ~100 with ~1-2 ulp RELATIVE accuracy (critical:
// SIREN activations contract to ~1e-7; MUFU.SIN's absolute error destroys them)
// ---------------------------------------------------------------------------
__device__ __forceinline__ float sin_acc(float x) {
    const float INV_PI = 0.318309886183790672f;
    const float PI_HI  = 3.14159274101257324f;     // fp32(pi)
    const float PI_LO  = -8.74227765734758577e-8f; // pi - PI_HI
    float q = rintf(x * INV_PI);
    float r = fmaf(-q, PI_HI, x);
    r = fmaf(-q, PI_LO, r);
    float r2 = r * r;
    float p = 1.58969104521e-10f;
    p = fmaf(p, r2, -2.50507477726e-8f);
    p = fmaf(p, r2, 2.75573146014e-6f);
    p = fmaf(p, r2, -1.98412701138e-4f);
    p = fmaf(p, r2, 8.33333376795e-3f);
    p = fmaf(p, r2, -1.66666671634e-1f);
    float s = fmaf(p * r2, r, r);      // r + r^3 * P(r^2)
    int qi = (int)q;
    return (qi & 1) ? -s : s;
}

// ---------------------------------------------------------------------------
// Kernel 1: Instant-NGP hash grid encoding
// ---------------------------------------------------------------------------
__global__ void hash_kernel(const float* __restrict__ pts,
                            const float* __restrict__ table,
                            int N, Res8 R) {
    int n = blockIdx.x * blockDim.x + threadIdx.x;
    if (n >= N) return;
    float px = (pts[3 * n + 0] + 1.0f) * 0.5f;
    float py = (pts[3 * n + 1] + 1.0f) * 0.5f;
    float pz = (pts[3 * n + 2] + 1.0f) * 0.5f;
    const float4* tab4 = (const float4*)table;
#pragma unroll
    for (int l = 0; l < NUM_LEVELS; l++) {
        float res = R.r[l];
        float sx = px * res, sy = py * res, sz = pz * res;
        float bx = floorf(sx), by = floorf(sy), bz = floorf(sz);
        float fx = sx - bx, fy = sy - by, fz = sz - bz;
        int ix = (int)bx, iy = (int)by, iz = (int)bz;
        unsigned hx0 = (unsigned)ix;
        unsigned hx1 = (unsigned)(ix + 1);
        unsigned hy0 = (unsigned)iy       * 2654435761u;
        unsigned hy1 = (unsigned)(iy + 1) * 2654435761u;
        unsigned hz0 = (unsigned)iz       * 805459861u;
        unsigned hz1 = (unsigned)(iz + 1) * 805459861u;
        const float4* t = tab4 + (size_t)l * TABLE_SIZE;
        float4 g000 = t[(hx0 ^ hy0 ^ hz0) & TMASK];
        float4 g001 = t[(hx0 ^ hy0 ^ hz1) & TMASK];
        float4 g010 = t[(hx0 ^ hy1 ^ hz0) & TMASK];
        float4 g011 = t[(hx0 ^ hy1 ^ hz1) & TMASK];
        float4 g100 = t[(hx1 ^ hy0 ^ hz0) & TMASK];
        float4 g101 = t[(hx1 ^ hy0 ^ hz1) & TMASK];
        float4 g110 = t[(hx1 ^ hy1 ^ hz0) & TMASK];
        float4 g111 = t[(hx1 ^ hy1 ^ hz1) & TMASK];
        float ux = 1.0f - fx, uy = 1.0f - fy, uz = 1.0f - fz;
        float w000 = ux * uy * uz, w001 = ux * uy * fz;
        float w010 = ux * fy * uz, w011 = ux * fy * fz;
        float w100 = fx * uy * uz, w101 = fx * uy * fz;
        float w110 = fx * fy * uz, w111 = fx * fy * fz;
        float a0 = w000 * g000.x + w001 * g001.x + w010 * g010.x + w011 * g011.x
                 + w100 * g100.x + w101 * g101.x + w110 * g110.x + w111 * g111.x;
        float a1 = w000 * g000.y + w001 * g001.y + w010 * g010.y + w011 * g011.y
                 + w100 * g100.y + w101 * g101.y + w110 * g110.y + w111 * g111.y;
        float a2 = w000 * g000.z + w001 * g001.z + w010 * g010.z + w011 * g011.z
                 + w100 * g100.z + w101 * g101.z + w110 * g110.z + w111 * g111.z;
        float a3 = w000 * g000.w + w001 * g001.w + w010 * g010.w + w011 * g011.w
                 + w100 * g100.w + w101 * g101.w + w110 * g110.w + w111 * g111.w;
        g_enc[(size_t)(l * 4 + 0) * N + n] = a0;
        g_enc[(size_t)(l * 4 + 1) * N + n] = a1;
        g_enc[(size_t)(l * 4 + 2) * N + n] = a2;
        g_enc[(size_t)(l * 4 + 3) * N + n] = a3;
    }
}

// ---------------------------------------------------------------------------
// Kernel 2: fused SIREN MLPs, weights + per-thread activations in SMEM
// ---------------------------------------------------------------------------
#define O_W1IN  0        // 32*64 = 2048
#define O_B1IN  2048     // 64
#define O_W1H   2112     // 4*64*64 = 16384
#define O_B1H   18496    // 4*64 = 256
#define O_W1OUT 18752    // 64*16 = 1024
#define O_B1OUT 19776    // 16
#define O_W2IN  19792    // 47*64 = 3008
#define O_B2IN  22800    // 64
#define O_W2H   22864    // 2*64*64 = 8192
#define O_B2H   31056    // 2*64 = 128
#define O_W2OUT 31184    // 64
#define O_B2OUT 31248    // 1
#define O_X     31264    // 64*TPB activation columns
#define SM_FLOATS (O_X + 64 * TPB)
#define SM_BYTES  (SM_FLOATS * sizeof(float))

// y = sin(scale*(x @ W + b)) with f32x2-packed accumulators (bit-identical
// to scalar). W is [IN][64] row-major in SMEM; biases/weights 8B-aligned.
template <int IN>
__device__ __forceinline__ void layer64(const float* __restrict__ W,
                                        const float* __restrict__ B,
                                        float* __restrict__ xb, int tid,
                                        float scale) {
    u64t acc[32];
    const u64t* b2 = (const u64t*)B;
#pragma unroll
    for (int j = 0; j < 32; j++) acc[j] = b2[j];
#pragma unroll 2
    for (int i = 0; i < IN; i++) {
        u64t xi2 = pack2(xb[i * TPB + tid]);
        const u64t* w2 = (const u64t*)(W + i * 64);
#pragma unroll
        for (int q = 0; q < 32; q++) acc[q] = ffma2(xi2, w2[q], acc[q]);
    }
#pragma unroll
    for (int j = 0; j < 32; j++) {
        float2 v = unpack2(acc[j]);
        xb[(2 * j + 0) * TPB + tid] = sin_acc(scale * v.x);
        xb[(2 * j + 1) * TPB + tid] = sin_acc(scale * v.y);
    }
}

__global__ void __launch_bounds__(TPB, 1) mlp_kernel(
    const float* __restrict__ s1_win,  const float* __restrict__ s1_bin,
    const float* __restrict__ s1_wh,   const float* __restrict__ s1_bh,
    const float* __restrict__ s1_wout, const float* __restrict__ s1_bout,
    const float* __restrict__ s2_win,  const float* __restrict__ s2_bin,
    const float* __restrict__ s2_wh,   const float* __restrict__ s2_bh,
    const float* __restrict__ s2_wout, const float* __restrict__ s2_bout,
    float* __restrict__ out, int N) {
    extern __shared__ float sm[];
    int tid = threadIdx.x;
#define CPY(off, src, cnt) \
    for (int i = tid; i < (cnt); i += TPB) sm[(off) + i] = (src)[i];
    CPY(O_W1IN,  s1_win,  2048);
    CPY(O_B1IN,  s1_bin,  64);
    CPY(O_W1H,   s1_wh,   16384);
    CPY(O_B1H,   s1_bh,   256);
    CPY(O_W1OUT, s1_wout, 1024);
    CPY(O_B1OUT, s1_bout, 16);
    CPY(O_W2IN,  s2_win,  3008);
    CPY(O_B2IN,  s2_bin,  64);
    CPY(O_W2H,   s2_wh,   8192);
    CPY(O_B2H,   s2_bh,   128);
    CPY(O_W2OUT, s2_wout, 64);
    CPY(O_B2OUT, s2_bout, 1);
#undef CPY
    __syncthreads();

    float* xb = sm + O_X;
    for (int n = blockIdx.x * TPB + tid; n < N; n += gridDim.x * TPB) {
        // SIREN 1 input: encoding (32)
#pragma unroll
        for (int i = 0; i < 32; i++) xb[i * TPB + tid] = g_enc[(size_t)i * N + n];

        layer64<32>(sm + O_W1IN, sm + O_B1IN, xb, tid, W0F);
#pragma unroll
        for (int l = 0; l < 4; l++)
            layer64<64>(sm + O_W1H + l * 4096, sm + O_B1H + l * 64, xb, tid, 1.0f);

        // SIREN 1 output layer: 64 -> 16, no activation (scalar; 4% of work)
        float o[16];
#pragma unroll
        for (int j = 0; j < 16; j++) o[j] = sm[O_B1OUT + j];
        for (int i = 0; i < 64; i++) {
            float xi = xb[i * TPB + tid];
            const float4* w4 = (const float4*)(sm + O_W1OUT + i * 16);
#pragma unroll
            for (int q = 0; q < 4; q++) {
                float4 wv = w4[q];
                o[4 * q + 0] += xi * wv.x;
                o[4 * q + 1] += xi * wv.y;
                o[4 * q + 2] += xi * wv.z;
                o[4 * q + 3] += xi * wv.w;
            }
        }
        float density = fmaxf(o[0], 0.0f);

        // SIREN 2 input: [o[1..15], enc[0..31]] = 47
#pragma unroll
        for (int i = 0; i < 15; i++) xb[i * TPB + tid] = o[i + 1];
#pragma unroll
        for (int i = 0; i < 32; i++)
            xb[(15 + i) * TPB + tid] = g_enc[(size_t)i * N + n];

        layer64<47>(sm + O_W2IN, sm + O_B2IN, xb, tid, W0F);
#pragma unroll
        for (int l = 0; l < 2; l++)
            layer64<64>(sm + O_W2H + l * 4096, sm + O_B2H + l * 64, xb, tid, 1.0f);

        // SIREN 2 output layer: 64 -> 1
        float sc = sm[O_B2OUT];
        for (int i = 0; i < 64; i++) sc += xb[i * TPB + tid] * sm[O_W2OUT + i];

        out[n] = sc;          // scalar
        out[N + n] = density; // density
    }
}

// ---------------------------------------------------------------------------
extern "C" void kernel_launch(void* const* d_in, const int* in_sizes, int n_in,
                              void* d_out, int out_size) {
    const float* pts     = (const float*)d_in[0];
    const float* table   = (const float*)d_in[1];
    const float* s1_win  = (const float*)d_in[2];
    const float* s1_bin  = (const float*)d_in[3];
    const float* s1_wh   = (const float*)d_in[4];
    const float* s1_bh   = (const float*)d_in[5];
    const float* s1_wout = (const float*)d_in[6];
    const float* s1_bout = (const float*)d_in[7];
    const float* s2_win  = (const float*)d_in[8];
    const float* s2_bin  = (const float*)d_in[9];
    const float* s2_wh   = (const float*)d_in[10];
    const float* s2_bh   = (const float*)d_in[11];
    const float* s2_wout = (const float*)d_in[12];
    const float* s2_bout = (const float*)d_in[13];
    float* out = (float*)d_out;

    int N = in_sizes[0] / 3;

    // Resolutions in host double, EXACTLY mirroring numpy:
    // b = exp((ln 4096 - ln 16)/7); res_l = floor(16 * b**l)
    Res8 R;
    double b = exp((log(4096.0) - log(16.0)) / 7.0);
    for (int l = 0; l < 8; l++) R.r[l] = (float)floor(16.0 * pow(b, (double)l));

    hash_kernel<<<(N + TPB - 1) / TPB, TPB>>>(pts, table, N, R);

    cudaFuncSetAttribute(mlp_kernel, cudaFuncAttributeMaxDynamicSharedMemorySize,
                         (int)SM_BYTES);
    mlp_kernel<<<NSM, TPB, SM_BYTES>>>(s1_win, s1_bin, s1_wh, s1_bh, s1_wout,
                                       s1_bout, s2_win, s2_bin, s2_wh, s2_bh,
                                       s2_wout, s2_bout, out, N);
}